// round 8
// baseline (speedup 1.0000x reference)
#include <cuda_runtime.h>
#include <cstdint>

// Problem dims (fixed by the reference)
#define T_ 512
#define B_ 128
#define D_ 256
#define H_ 256

typedef unsigned long long ull;

// ---------------------------------------------------------------------------
// f32x2 helpers (sm_100 packed fp32 pipe: 2 FMAs per instruction)
// ---------------------------------------------------------------------------
__device__ __forceinline__ ull f32x2_pack(float x, float y) {
    ull d;
    asm("mov.b64 %0, {%1, %2};"
        : "=l"(d) : "r"(__float_as_uint(x)), "r"(__float_as_uint(y)));
    return d;
}
__device__ __forceinline__ void f32x2_unpack(ull a, float& x, float& y) {
    unsigned lo, hi;
    asm("mov.b64 {%0, %1}, %2;" : "=r"(lo), "=r"(hi) : "l"(a));
    x = __uint_as_float(lo);
    y = __uint_as_float(hi);
}
__device__ __forceinline__ void ffma2(ull& d, ull a, ull b) {
    asm("fma.rn.f32x2 %0, %1, %2, %0;" : "+l"(d) : "l"(a), "l"(b));
}
__device__ __forceinline__ void fmul2(ull& d, ull a, ull b) {
    asm("mul.rn.f32x2 %0, %1, %2;" : "=l"(d) : "l"(a), "l"(b));
}

// ---------------------------------------------------------------------------
// Phase 1: Z[m][n] = sum_d X[m][d] * Wi[n][d] + bh[n]   (m = t*B + b)
// Written directly into d_out (same shape as the final output). Unchanged.
// ---------------------------------------------------------------------------
__global__ void __launch_bounds__(256, 2) rnn_wx_kernel(
    const float* __restrict__ X, const float* __restrict__ Wi,
    const float* __restrict__ bh, float* __restrict__ out)
{
    __shared__ __align__(16) float As[16][132];  // [k][m], padded
    __shared__ __align__(16) float Bs[16][132];  // [k][n], padded

    const int tid = threadIdx.x;
    const int tx = tid & 15;   // col group (8 cols each)
    const int ty = tid >> 4;   // row group (8 rows each)
    const int bx = blockIdx.x & 1;
    const int by = blockIdx.x >> 1;
    const int m0 = by * 128;
    const int n0 = bx * 128;

    const float* Ag = X  + (size_t)m0 * D_;
    const float* Bg = Wi + (size_t)n0 * D_;

    ull acc[8][4];
#pragma unroll
    for (int i = 0; i < 8; i++)
#pragma unroll
        for (int j = 0; j < 4; j++) acc[i][j] = 0ull;

    const int lr = tid >> 2;          // 0..63 (plus +64 pass)
    const int lk = (tid & 3) * 4;     // k offset of this thread's float4

    for (int k0 = 0; k0 < D_; k0 += 16) {
#pragma unroll
        for (int p = 0; p < 128; p += 64) {
            float4 va = *(const float4*)(Ag + (size_t)(lr + p) * D_ + k0 + lk);
            As[lk + 0][lr + p] = va.x;
            As[lk + 1][lr + p] = va.y;
            As[lk + 2][lr + p] = va.z;
            As[lk + 3][lr + p] = va.w;
            float4 vb = *(const float4*)(Bg + (size_t)(lr + p) * D_ + k0 + lk);
            Bs[lk + 0][lr + p] = vb.x;
            Bs[lk + 1][lr + p] = vb.y;
            Bs[lk + 2][lr + p] = vb.z;
            Bs[lk + 3][lr + p] = vb.w;
        }
        __syncthreads();

#pragma unroll
        for (int k = 0; k < 16; k++) {
            float4 a0 = *(const float4*)&As[k][ty * 8];
            float4 a1 = *(const float4*)&As[k][ty * 8 + 4];
            ulonglong2 q0 = *(const ulonglong2*)&Bs[k][tx * 8];
            ulonglong2 q1 = *(const ulonglong2*)&Bs[k][tx * 8 + 4];
            ull bv[4];
            bv[0] = q0.x; bv[1] = q0.y; bv[2] = q1.x; bv[3] = q1.y;
            ull ad[8];
            ad[0] = f32x2_pack(a0.x, a0.x);
            ad[1] = f32x2_pack(a0.y, a0.y);
            ad[2] = f32x2_pack(a0.z, a0.z);
            ad[3] = f32x2_pack(a0.w, a0.w);
            ad[4] = f32x2_pack(a1.x, a1.x);
            ad[5] = f32x2_pack(a1.y, a1.y);
            ad[6] = f32x2_pack(a1.z, a1.z);
            ad[7] = f32x2_pack(a1.w, a1.w);
#pragma unroll
            for (int i = 0; i < 8; i++) {
#pragma unroll
                for (int j = 0; j < 4; j++) ffma2(acc[i][j], ad[i], bv[j]);
            }
        }
        __syncthreads();
    }

    // Epilogue: add bias, store
    float4 bb0 = *(const float4*)(bh + n0 + tx * 8);
    float4 bb1 = *(const float4*)(bh + n0 + tx * 8 + 4);
#pragma unroll
    for (int i = 0; i < 8; i++) {
        float c0, c1, c2, c3, c4, c5, c6, c7;
        f32x2_unpack(acc[i][0], c0, c1);
        f32x2_unpack(acc[i][1], c2, c3);
        f32x2_unpack(acc[i][2], c4, c5);
        f32x2_unpack(acc[i][3], c6, c7);
        float4 o0 = make_float4(c0 + bb0.x, c1 + bb0.y, c2 + bb0.z, c3 + bb0.w);
        float4 o1 = make_float4(c4 + bb1.x, c5 + bb1.y, c6 + bb1.z, c7 + bb1.w);
        float* orow = out + (size_t)(m0 + ty * 8 + i) * H_ + n0 + tx * 8;
        *(float4*)(orow)     = o0;
        *(float4*)(orow + 4) = o1;
    }
}

// ---------------------------------------------------------------------------
// Phase 2: recurrence. 32 clusters x 2 CTAs, 512 thr/CTA, 4 batch rows per
// cluster (latency chain amortized over 4 independent rows).
//   warp w owns cols colbase = rank*128 + w*8
//   lane l owns k-set {4l..4l+3} U {128+4l..128+4l+3}
//   per lane partials: p[4 rows][8 cols] = 32 -> perfect 5-round butterfly,
//   every lane ends with ONE distinct (row,col): row=(lane>>3)&3, col=lane&7.
// Sync: single mbarrier per CTA, 1024 arrivals/phase (512 local + 512 peer);
// every thread: STS local h + DSMEM peer h + STG out, then release-arrives
// on BOTH mbars. Wait(acquire) subsumes __syncthreads.
// ---------------------------------------------------------------------------
__global__ void __cluster_dims__(2, 1, 1) __launch_bounds__(512, 1)
rnn_rec_kernel(const float* __restrict__ h0, const float* __restrict__ Wh,
               float* __restrict__ out)
{
    __shared__ __align__(16) float h_sm[2][4][H_];  // [buf][row][k]
    __shared__ __align__(8) ull mbar;

    const int tid  = threadIdx.x;
    const int warp = tid >> 5;
    const int lane = tid & 31;
    unsigned rank;
    asm("mov.u32 %0, %%cluster_ctarank;" : "=r"(rank));
    const int cid = blockIdx.x >> 1;
    const int b0  = cid * 4;
    const int colbase = (int)rank * 128 + warp * 8;
    const int l4 = lane * 4;

    // Wh: 8 cols x 8 k-values -> 32 f32x2 regs
    ull w[8][4];
#pragma unroll
    for (int cc = 0; cc < 8; cc++) {
        const float* wr = Wh + (size_t)(colbase + cc) * H_;
        ulonglong2 qa = *(const ulonglong2*)(wr + l4);
        ulonglong2 qb = *(const ulonglong2*)(wr + 128 + l4);
        w[cc][0] = qa.x; w[cc][1] = qa.y;
        w[cc][2] = qb.x; w[cc][3] = qb.y;
    }

    // Init h buffer 0 with h0: 4 rows x 256 = 1024 entries / 512 threads
    {
#pragma unroll
        for (int i = 0; i < 2; i++) {
            const int idx = tid + i * 512;
            const int row = idx >> 8;
            const int k   = idx & 255;
            h_sm[0][row][k] = h0[(size_t)(b0 + row) * H_ + k];
        }
    }

    // mbarrier: 1024 arrivals per phase (512 local + 512 remote)
    if (tid == 0) {
        unsigned ma;
        asm("{ .reg .u64 t; cvta.to.shared.u64 t, %1; cvt.u32.u64 %0, t; }"
            : "=r"(ma) : "l"(&mbar));
        asm volatile("mbarrier.init.shared.b64 [%0], 1024;" ::"r"(ma)
                     : "memory");
    }

    // Output mapping for this lane (valid after the butterfly)
    const int orow = (lane >> 3) & 3;
    const int ocol = colbase + (lane & 7);

    // Z prefetch for t=0
    float xi = out[(size_t)(b0 + orow) * H_ + ocol];

    // Local/peer shared addresses
    unsigned h_loc, mb_loc;
    asm("{ .reg .u64 t; cvta.to.shared.u64 t, %1; cvt.u32.u64 %0, t; }"
        : "=r"(h_loc) : "l"(&h_sm[0][0][0]));
    asm("{ .reg .u64 t; cvta.to.shared.u64 t, %1; cvt.u32.u64 %0, t; }"
        : "=r"(mb_loc) : "l"(&mbar));
    unsigned h_rem, mb_rem;
    asm("mapa.shared::cluster.u32 %0, %1, %2;"
        : "=r"(h_rem) : "r"(h_loc), "r"(rank ^ 1u));
    asm("mapa.shared::cluster.u32 %0, %1, %2;"
        : "=r"(mb_rem) : "r"(mb_loc), "r"(rank ^ 1u));

    __syncthreads();
    // One-time cluster barrier: both CTAs' mbar init + h buffers visible
    asm volatile("barrier.cluster.arrive.aligned;" ::: "memory");
    asm volatile("barrier.cluster.wait.aligned;" ::: "memory");

#pragma unroll 1
    for (int t = 0; t < T_; t++) {
        const int buf = t & 1;

        // partials p[row][col] for this lane's 8-k slice
        float p[4][8];
#pragma unroll
        for (int r = 0; r < 4; r++) {
            ulonglong2 qa = *(const ulonglong2*)&h_sm[buf][r][l4];
            ulonglong2 qb = *(const ulonglong2*)&h_sm[buf][r][128 + l4];
#pragma unroll
            for (int cc = 0; cc < 8; cc++) {
                ull acc;
                fmul2(acc, qa.x, w[cc][0]);
                ffma2(acc, qa.y, w[cc][1]);
                ffma2(acc, qb.x, w[cc][2]);
                ffma2(acc, qb.y, w[cc][3]);
                float x, y;
                f32x2_unpack(acc, x, y);
                p[r][cc] = x + y;
            }
        }

        // 5-round value-halving butterfly: 32 partials -> 1 per lane
        // R1 (xor16): split row-hi (r>=2)
        float s1[16];
        {
            const bool hi = (lane & 16) != 0;
#pragma unroll
            for (int j = 0; j < 16; j++) {
                const int r0 = j >> 3, c = j & 7;
                float keep = hi ? p[r0 + 2][c] : p[r0][c];
                float give = hi ? p[r0][c] : p[r0 + 2][c];
                s1[j] = keep + __shfl_xor_sync(0xffffffffu, give, 16);
            }
        }
        // R2 (xor8): split row-lo
        float s2[8];
        {
            const bool hi = (lane & 8) != 0;
#pragma unroll
            for (int c = 0; c < 8; c++) {
                float keep = hi ? s1[8 + c] : s1[c];
                float give = hi ? s1[c] : s1[8 + c];
                s2[c] = keep + __shfl_xor_sync(0xffffffffu, give, 8);
            }
        }
        // R3 (xor4): split col bit2
        float s3[4];
        {
            const bool hi = (lane & 4) != 0;
#pragma unroll
            for (int j = 0; j < 4; j++) {
                float keep = hi ? s2[4 + j] : s2[j];
                float give = hi ? s2[j] : s2[4 + j];
                s3[j] = keep + __shfl_xor_sync(0xffffffffu, give, 4);
            }
        }
        // R4 (xor2): split col bit1
        float s4[2];
        {
            const bool hi = (lane & 2) != 0;
#pragma unroll
            for (int j = 0; j < 2; j++) {
                float keep = hi ? s3[2 + j] : s3[j];
                float give = hi ? s3[j] : s3[2 + j];
                s4[j] = keep + __shfl_xor_sync(0xffffffffu, give, 2);
            }
        }
        // R5 (xor1): split col bit0
        float s;
        {
            const bool hi = (lane & 1) != 0;
            float keep = hi ? s4[1] : s4[0];
            float give = hi ? s4[0] : s4[1];
            s = keep + __shfl_xor_sync(0xffffffffu, give, 1);
        }

        // sigmoid: exactly one (row,col) per lane
        const float hn = 1.0f / (1.0f + __expf(-(xi + s)));
        const int nb = buf ^ 1;

        // local h
        h_sm[nb][orow][ocol] = hn;
        // peer h via DSMEM
        {
            const unsigned off =
                h_rem + (unsigned)(((nb * 4 + orow) * H_ + ocol) * 4);
            asm volatile("st.shared::cluster.f32 [%0], %1;"
                         ::"r"(off), "f"(hn) : "memory");
        }
        // emit h_t
        out[((size_t)t * B_ + b0 + orow) * H_ + ocol] = hn;
        // prefetch Z for t+1
        if (t + 1 < T_) {
            xi = out[((size_t)(t + 1) * B_ + b0 + orow) * H_ + ocol];
        }

        // release-arrive on BOTH barriers (orders this thread's stores
        // at cluster scope); wait needs 512 local + 512 peer arrivals.
        asm volatile(
            "mbarrier.arrive.release.cluster.shared::cluster.b64 _, [%0];"
            ::"r"(mb_rem) : "memory");
        asm volatile(
            "mbarrier.arrive.release.cluster.shared::cluster.b64 _, [%0];"
            ::"r"(mb_loc) : "memory");

        // wait for all 1024 arrivals of this phase (acquire)
        {
            const unsigned parity = (unsigned)(t & 1);
            unsigned done;
            asm volatile(
                "{\n\t"
                ".reg .pred p;\n\t"
                "mbarrier.try_wait.parity.acquire.cluster.shared::cta.b64 p, [%1], %2;\n\t"
                "selp.b32 %0, 1, 0, p;\n\t"
                "}"
                : "=r"(done) : "r"(mb_loc), "r"(parity) : "memory");
            if (!done) {
                asm volatile(
                    "{\n\t"
                    ".reg .pred P1;\n\t"
                    "WL_%=:\n\t"
                    "mbarrier.try_wait.parity.acquire.cluster.shared::cta.b64 P1, [%0], %1, 0x989680;\n\t"
                    "@P1 bra.uni WD_%=;\n\t"
                    "bra.uni WL_%=;\n\t"
                    "WD_%=:\n\t"
                    "}"
                    ::"r"(mb_loc), "r"(parity) : "memory");
            }
        }
    }
}

// ---------------------------------------------------------------------------
// Launch
// ---------------------------------------------------------------------------
extern "C" void kernel_launch(void* const* d_in, const int* in_sizes, int n_in,
                              void* d_out, int out_size) {
    const float* X  = (const float*)d_in[0];
    const float* h0 = (const float*)d_in[1];
    const float* Wi = (const float*)d_in[2];
    const float* Wh = (const float*)d_in[3];
    const float* bh = (const float*)d_in[4];
    float* out = (float*)d_out;

    // Phase 1: Z = X @ Wi^T + bh  ->  d_out
    rnn_wx_kernel<<<1024, 256>>>(X, Wi, bh, out);

    // Phase 2: recurrence, in place over d_out (32 clusters x 2 CTAs)
    rnn_rec_kernel<<<64, 512>>>(h0, Wh, out);
}